// round 14
// baseline (speedup 1.0000x reference)
#include <cuda_runtime.h>
#include <cuda_fp16.h>
#include <cstdint>

// Problem constants
#define BATCH 256
#define LSEQ  128
#define E_EXP 64
#define D1    512
#define D2    512

// Tiling
#define BM 128
#define BN 128
#define BK 32              // k elements per stage (2 x k16 sub-chunks)
#define NKT (D1/BK)        // 16 stages
#define ASTR 40            // halves per A smem row (32 + 8 pad) -> conflict-free LDSM
#define BSTR 136           // halves per B smem row (128 + 8 pad) -> conflict-free LDSM

// fp16 scratch (static device arrays -- no allocation)
__device__ __half g_t1h[BATCH * LSEQ * D1];   // 32 MB
__device__ __half g_wh[E_EXP * D1 * D2];      // 32 MB

__device__ __forceinline__ unsigned sptr(const void* p) {
    unsigned a;
    asm("{ .reg .u64 t; cvta.to.shared.u64 t, %1; cvt.u32.u64 %0, t; }" : "=r"(a) : "l"(p));
    return a;
}
__device__ __forceinline__ void cpasync16(unsigned dst_s, const void* src) {
    asm volatile("cp.async.cg.shared.global [%0], [%1], 16;\n" :: "r"(dst_s), "l"(src));
}
__device__ __forceinline__ void cp_commit() {
    asm volatile("cp.async.commit_group;\n" ::: "memory");
}
template <int N>
__device__ __forceinline__ void cp_wait() {
    asm volatile("cp.async.wait_group %0;\n" :: "n"(N) : "memory");
}
__device__ __forceinline__ void ldmx4(unsigned* r, unsigned a) {
    asm volatile("ldmatrix.sync.aligned.m8n8.x4.shared.b16 {%0,%1,%2,%3}, [%4];"
                 : "=r"(r[0]), "=r"(r[1]), "=r"(r[2]), "=r"(r[3]) : "r"(a));
}
__device__ __forceinline__ void ldmx4t(unsigned* r, unsigned a) {
    asm volatile("ldmatrix.sync.aligned.m8n8.x4.trans.shared.b16 {%0,%1,%2,%3}, [%4];"
                 : "=r"(r[0]), "=r"(r[1]), "=r"(r[2]), "=r"(r[3]) : "r"(a));
}
__device__ __forceinline__ void mma16816(float* c, const unsigned* a, const unsigned* b) {
    asm volatile(
        "mma.sync.aligned.m16n8k16.row.col.f32.f16.f16.f32 "
        "{%0,%1,%2,%3}, {%4,%5,%6,%7}, {%8,%9}, {%0,%1,%2,%3};"
        : "+f"(c[0]), "+f"(c[1]), "+f"(c[2]), "+f"(c[3])
        : "r"(a[0]), "r"(a[1]), "r"(a[2]), "r"(a[3]), "r"(b[0]), "r"(b[1]));
}

__global__ void zero_out_kernel(float* o, int n) {
    int i = blockIdx.x * blockDim.x + threadIdx.x;
    if (i < n) o[i] = 0.0f;
}

__global__ void cvt_f2h_kernel(const float* __restrict__ src, __half* __restrict__ dst, int n) {
    int i = (blockIdx.x * blockDim.x + threadIdx.x) * 8;
    if (i < n) {
        float4 f0 = *(const float4*)(src + i);
        float4 f1 = *(const float4*)(src + i + 4);
        __half2 h[4];
        h[0] = __floats2half2_rn(f0.x, f0.y);
        h[1] = __floats2half2_rn(f0.z, f0.w);
        h[2] = __floats2half2_rn(f1.x, f1.y);
        h[3] = __floats2half2_rn(f1.z, f1.w);
        *(uint4*)(dst + i) = *(uint4*)h;
    }
}

// grid: (D2/BN = 4, BATCH = 256), block: 256 threads (8 warps, 4m x 2n warp grid)
__global__ __launch_bounds__(256, 2) void pdot_h4_kernel(
    const float* __restrict__ t2,
    const int*   __restrict__ pidx,
    float*       __restrict__ out)
{
    // static smem: 2*(128*40 + 32*136)*2 = 37888 bytes (<48KB, no attribute needed)
    __shared__ __align__(16) __half As[2][BM][ASTR];
    __shared__ __align__(16) __half Bs[2][BK][BSTR];

    const int b  = blockIdx.y;
    const int jc = blockIdx.x * BN;
    const int e  = pidx[b];

    const __half* Agh = g_t1h + (size_t)b * LSEQ * D1;
    const __half* Wgh = g_wh  + (size_t)e * D1 * D2;
    const float*  T2g = t2    + (size_t)b * LSEQ * D2;

    const int tid  = threadIdx.x;
    const int lane = tid & 31;
    const int warp = tid >> 5;
    const int gid  = lane >> 2;
    const int tig  = lane & 3;
    const int wm   = warp >> 1;     // 0..3 -> 32-row strip
    const int wn   = warp & 1;      // 0..1 -> 64-col strip

    // loader: 4 cp.async per thread per stage (A: 512 chunks, B: 512 chunks)
    auto load_stage = [&](int s, int k0) {
        #pragma unroll
        for (int i = 0; i < 2; ++i) {
            int v  = tid + i * 256;
            int ar = v >> 2,  ac2 = (v & 3) * 8;       // A row, 8-half chunk
            cpasync16(sptr(&As[s][ar][ac2]), Agh + (size_t)ar * D1 + k0 + ac2);
            int br2 = v >> 4, bc2 = (v & 15) * 8;      // B k-row, 8-half chunk
            cpasync16(sptr(&Bs[s][br2][bc2]), Wgh + (size_t)(k0 + br2) * D2 + jc + bc2);
        }
        cp_commit();
    };

    // per-thread ldmatrix offsets (proven mapping)
    const int a_row = ((lane >> 3) & 1) * 8 + (lane & 7);
    const int a_kch = (lane >> 4) * 8;
    const int b_kr  = ((lane >> 3) & 1) * 8 + (lane & 7);
    const int b_nch = (lane >> 4) * 8;

    float acc[2][8][4];
    #pragma unroll
    for (int mi = 0; mi < 2; ++mi)
        #pragma unroll
        for (int ni = 0; ni < 8; ++ni)
            #pragma unroll
            for (int r = 0; r < 4; ++r) acc[mi][ni][r] = 0.0f;

    // prologue: both buffers in flight
    load_stage(0, 0);
    load_stage(1, BK);

    for (int kt = 0; kt < NKT; ++kt) {
        if (kt == 0) cp_wait<1>();      // stage 0 done, stage 1 still loading
        else         cp_wait<0>();      // stage kt done (overlapped compute kt-1)
        __syncthreads();                // all warps: stage kt visible; buffer (kt+1)&1 free

        // refill the buffer consumed at kt-1 with stage kt+1... (kt+1)&1 == (kt-1)&1
        if (kt >= 1 && kt + 1 < NKT) load_stage((kt + 1) & 1, (kt + 1) * BK);

        const int s = kt & 1;
        #pragma unroll
        for (int kk = 0; kk < 2; ++kk) {
            const int k16 = kk * 16;
            unsigned af[2][4];
            #pragma unroll
            for (int mi = 0; mi < 2; ++mi) {
                int rb = wm * 32 + mi * 16;
                ldmx4(af[mi], sptr(&As[s][rb + a_row][k16 + a_kch]));
            }
            unsigned bf[8][2];
            #pragma unroll
            for (int p = 0; p < 4; ++p) {
                unsigned r[4];
                int n0 = wn * 64 + p * 16;
                ldmx4t(r, sptr(&Bs[s][k16 + b_kr][n0 + b_nch]));
                bf[2*p][0] = r[0]; bf[2*p][1] = r[1];
                bf[2*p+1][0] = r[2]; bf[2*p+1][1] = r[3];
            }
            #pragma unroll
            for (int mi = 0; mi < 2; ++mi)
                #pragma unroll
                for (int ni = 0; ni < 8; ++ni)
                    mma16816(acc[mi][ni], af[mi], bf[ni]);
        }
    }

    // fused epilogue: out[b,row] += sum_j acc(row,j) * t2[b,row,jc+j]
    float ps[4] = {0.f, 0.f, 0.f, 0.f};
    #pragma unroll
    for (int mi = 0; mi < 2; ++mi) {
        int r0 = wm * 32 + mi * 16 + gid;
        #pragma unroll
        for (int ni = 0; ni < 8; ++ni) {
            int c = jc + wn * 64 + ni * 8 + 2 * tig;
            float2 u = *(const float2*)(T2g + (size_t)r0 * D2 + c);
            float2 v = *(const float2*)(T2g + (size_t)(r0 + 8) * D2 + c);
            ps[mi * 2 + 0] += acc[mi][ni][0] * u.x + acc[mi][ni][1] * u.y;
            ps[mi * 2 + 1] += acc[mi][ni][2] * v.x + acc[mi][ni][3] * v.y;
        }
    }
    #pragma unroll
    for (int r = 0; r < 4; ++r) {
        ps[r] += __shfl_xor_sync(0xffffffffu, ps[r], 1);
        ps[r] += __shfl_xor_sync(0xffffffffu, ps[r], 2);
    }
    if (tig == 0) {
        #pragma unroll
        for (int mi = 0; mi < 2; ++mi) {
            int r0 = wm * 32 + mi * 16 + gid;
            atomicAdd(&out[b * LSEQ + r0],     ps[mi * 2 + 0]);
            atomicAdd(&out[b * LSEQ + r0 + 8], ps[mi * 2 + 1]);
        }
    }
}

extern "C" void kernel_launch(void* const* d_in, const int* in_sizes, int n_in,
                              void* d_out, int out_size)
{
    (void)in_sizes; (void)n_in; (void)out_size;
    const float* t1  = (const float*)d_in[0];
    const float* t2  = (const float*)d_in[1];
    const int*   idx = (const int*)  d_in[2];
    const float* W   = (const float*)d_in[3];
    float* out = (float*)d_out;

    __half* t1h = nullptr;  __half* wh = nullptr;
    cudaGetSymbolAddress((void**)&t1h, g_t1h);
    cudaGetSymbolAddress((void**)&wh,  g_wh);

    const int n_t1 = BATCH * LSEQ * D1;
    const int n_w  = E_EXP * D1 * D2;
    cvt_f2h_kernel<<<n_t1 / 8 / 256, 256>>>(t1, t1h, n_t1);
    cvt_f2h_kernel<<<n_w  / 8 / 256, 256>>>(W,  wh,  n_w);

    const int n = BATCH * LSEQ;
    zero_out_kernel<<<(n + 255) / 256, 256>>>(out, n);

    dim3 grid(D2 / BN, BATCH);
    pdot_h4_kernel<<<grid, 256>>>(t2, idx, out);
}